// round 1
// baseline (speedup 1.0000x reference)
#include <cuda_runtime.h>
#include <cuda_fp16.h>
#include <mma.h>

using namespace nvcuda;

#define B_  128
#define T_  2048
#define H_  200
#define HP  208     // H padded to multiple of 16
#define LD  216     // smem leading dim (halves) -> conflict-friendly ldmatrix strides
#define G4  800     // 4*H

// -------- device scratch (no allocations allowed) --------
__device__ __align__(16) half  g_Ua[HP * LD];      // Ua padded, fp16, [n][k]
__device__ float g_qadd[B_ * HP];                  // q_proj + ba + bua, padded
__device__ float g_hpre[B_ * G4];                  // h0 @ W_hh.T + b_hh
__device__ float g_sc[B_ * T_];                    // scores -> attn (in place)
__device__ float g_ctxp[16 * B_ * H_];             // context partials (deterministic reduce)

__device__ __forceinline__ float fast_tanh(float x) {
    float e = __expf(2.f * x);                 // MUFU.EX2; overflow -> inf -> tanh=1 ok
    return 1.f - __fdividef(2.f, e + 1.f);
}
__device__ __forceinline__ float fast_sig(float x) {
    return __fdividef(1.f, 1.f + __expf(-x));
}

// -------- prep: Ua -> fp16 padded [HP][LD] --------
__global__ void prep_ua(const float* __restrict__ Ua) {
    int n = blockIdx.x, k = threadIdx.x;
    if (k < LD) {
        float v = (n < H_ && k < H_) ? Ua[n * H_ + k] : 0.f;
        g_Ua[n * LD + k] = __float2half(v);
    }
}

// -------- prep: qadd[b,:] = h0[b]@Wa.T + ba + bua ; h_pre[b,:] = h0[b]@W_hh.T + b_hh --------
__global__ void prep_qh(const float* __restrict__ h0, const float* __restrict__ Wa,
                        const float* __restrict__ ba, const float* __restrict__ bua,
                        const float* __restrict__ Whh, const float* __restrict__ bhh) {
    int b = blockIdx.x, tid = threadIdx.x;
    __shared__ float hs[H_];
    if (tid < H_) hs[tid] = h0[b * H_ + tid];
    __syncthreads();
    if (tid < HP) {
        float acc = 0.f;
        if (tid < H_) {
            acc = ba[tid] + bua[tid];
            const float* w = Wa + tid * H_;
            #pragma unroll 4
            for (int k = 0; k < H_; k++) acc += hs[k] * w[k];
        }
        g_qadd[b * HP + tid] = acc;
    }
    for (int g = tid; g < G4; g += 256) {
        float acc = bhh[g];
        const float* w = Whh + g * H_;
        #pragma unroll 4
        for (int k = 0; k < H_; k++) acc += hs[k] * w[k];
        g_hpre[b * G4 + g] = acc;
    }
}

// -------- fused scores: tanh(qadd + enc@Ua.T) . Va + bva, never materializing k_proj --------
// grid: 2048 CTAs (16 per batch, 128 t-rows each), 256 threads (8 warps, 16 rows/warp)
__global__ void __launch_bounds__(256) scores_k(const float* __restrict__ enc,
                                                const float* __restrict__ Va,
                                                const float* __restrict__ bva) {
    extern __shared__ char smraw[];
    half*  As  = (half*)smraw;                 // 128 x LD fp16 enc tile   (55296 B)
    half*  Bs  = As + 128 * LD;                // HP x LD fp16 Ua          (89856 B)
    float* scr = (float*)(Bs + HP * LD);       // 8 warps x 16 x 20 scratch (10240 B)
    float* qas = scr + 8 * 320;                // HP
    float* vas = qas + HP;                     // HP

    int tid = threadIdx.x;
    int b   = blockIdx.x >> 4;
    int t0  = (blockIdx.x & 15) << 7;

    // stage Ua (fp16, already padded) via int4 copies
    {
        const int4* s4 = (const int4*)g_Ua;
        int4* d4 = (int4*)Bs;
        for (int i = tid; i < (HP * LD * 2) / 16; i += 256) d4[i] = s4[i];
    }
    if (tid < HP) {
        qas[tid] = g_qadd[b * HP + tid];
        vas[tid] = (tid < H_) ? Va[tid] : 0.f;
    }
    // stage 128 encoder rows, fp32 -> fp16, pad K to LD
    const float* encb = enc + (size_t)(b * T_ + t0) * H_;
    int r0w = tid >> 6, lane = tid & 63;
    for (int rr = r0w; rr < 128; rr += 4) {
        const float* row = encb + rr * H_;
        for (int k = lane; k < LD; k += 64)
            As[rr * LD + k] = __float2half(k < H_ ? row[k] : 0.f);
    }
    __syncthreads();

    int warp = tid >> 5, lid = tid & 31;
    float part = 0.f;
    float* scw = scr + warp * 320;
    const half* Aw = As + (warp * 16) * LD;
    int rr = lid >> 1, cc = (lid & 1) * 8;

    for (int nt = 0; nt < 13; nt++) {
        wmma::fragment<wmma::accumulator, 16, 16, 16, float> acc;
        wmma::fill_fragment(acc, 0.f);
        #pragma unroll
        for (int kt = 0; kt < 13; kt++) {
            wmma::fragment<wmma::matrix_a, 16, 16, 16, half, wmma::row_major> af;
            wmma::fragment<wmma::matrix_b, 16, 16, 16, half, wmma::col_major> bf;
            wmma::load_matrix_sync(af, Aw + kt * 16, LD);
            wmma::load_matrix_sync(bf, Bs + (nt * 16) * LD + kt * 16, LD);
            wmma::mma_sync(acc, af, bf, acc);
        }
        wmma::store_matrix_sync(scw, acc, 20, wmma::mem_row_major);
        __syncwarp();
        int nb = nt * 16 + cc;
        #pragma unroll
        for (int c = 0; c < 8; c++) {
            float v = scw[rr * 20 + cc + c];
            part += vas[nb + c] * fast_tanh(qas[nb + c] + v);
        }
        __syncwarp();
    }
    part += __shfl_xor_sync(0xffffffffu, part, 1);
    if ((lid & 1) == 0)
        g_sc[b * T_ + t0 + warp * 16 + rr] = part + bva[0];
}

// -------- softmax over T per batch, in place --------
__global__ void softmax_k() {
    int b = blockIdx.x, tid = threadIdx.x;
    __shared__ float red[256];
    float* s = g_sc + b * T_;
    float m = -1e30f;
    for (int i = tid; i < T_; i += 256) m = fmaxf(m, s[i]);
    red[tid] = m; __syncthreads();
    for (int st = 128; st > 0; st >>= 1) { if (tid < st) red[tid] = fmaxf(red[tid], red[tid + st]); __syncthreads(); }
    m = red[0]; __syncthreads();
    float sum = 0.f;
    for (int i = tid; i < T_; i += 256) { float e = __expf(s[i] - m); s[i] = e; sum += e; }
    red[tid] = sum; __syncthreads();
    for (int st = 128; st > 0; st >>= 1) { if (tid < st) red[tid] += red[tid + st]; __syncthreads(); }
    float inv = 1.f / red[0];
    for (int i = tid; i < T_; i += 256) s[i] *= inv;
}

// -------- context partials: ctxp[s,b,:] = sum_{t in chunk s} attn[b,t]*enc[b,t,:] --------
__global__ void context_k(const float* __restrict__ enc) {
    int b = blockIdx.x, s = blockIdx.y, tid = threadIdx.x;
    __shared__ float w[128];
    if (tid < 128) w[tid] = g_sc[b * T_ + s * 128 + tid];
    __syncthreads();
    if (tid < H_) {
        const float* p = enc + (size_t)(b * T_ + s * 128) * H_ + tid;
        float acc = 0.f;
        #pragma unroll 8
        for (int t = 0; t < 128; t++) acc += w[t] * p[(size_t)t * H_];
        g_ctxp[(s * B_ + b) * H_ + tid] = acc;
    }
}

// -------- decoder: gates_base once, then 5 tiny steps (state never recurs except via y->x) --------
__global__ void decoder_k(const float* __restrict__ x,  const float* __restrict__ c0,
                          const float* __restrict__ Wih, const float* __restrict__ bih,
                          const float* __restrict__ W1, const float* __restrict__ b1,
                          const float* __restrict__ W2, const float* __restrict__ b2,
                          const float* __restrict__ W3, const float* __restrict__ b3,
                          float* __restrict__ out) {
    int b = blockIdx.x, tid = threadIdx.x;
    __shared__ float ctx[H_], gb[G4], r0s[H_], l1s[100], l2s[50];
    __shared__ float xs;
    if (tid < H_) {
        float a = 0.f;
        #pragma unroll
        for (int j = 0; j < 16; j++) a += g_ctxp[(j * B_ + b) * H_ + tid];
        ctx[tid] = a;
    }
    if (tid == 0) xs = x[b];
    __syncthreads();
    for (int g = tid; g < G4; g += 256) {
        float acc = bih[g] + g_hpre[b * G4 + g];
        const float* w = Wih + g * 201 + 1;
        #pragma unroll 4
        for (int h = 0; h < H_; h++) acc += ctx[h] * w[h];
        gb[g] = acc;
    }
    __syncthreads();
    float xv = xs;
    for (int st = 0; st < 5; st++) {
        if (tid < H_) {
            float gi = gb[tid]       + xv * Wih[(tid)       * 201];
            float gf = gb[200 + tid] + xv * Wih[(200 + tid) * 201];
            float gg = gb[400 + tid] + xv * Wih[(400 + tid) * 201];
            float go = gb[600 + tid] + xv * Wih[(600 + tid) * 201];
            float c  = fast_sig(gf) * c0[b * H_ + tid] + fast_sig(gi) * fast_tanh(gg);
            float h  = fast_sig(go) * fast_tanh(c);
            r0s[tid] = fmaxf(h, 0.f);
        }
        __syncthreads();
        if (tid < 100) {
            float acc = b1[tid];
            const float* w = W1 + tid * H_;
            #pragma unroll 4
            for (int h = 0; h < H_; h++) acc += r0s[h] * w[h];
            l1s[tid] = fmaxf(acc, 0.f);
        }
        __syncthreads();
        if (tid < 50) {
            float acc = b2[tid];
            const float* w = W2 + tid * 100;
            #pragma unroll 4
            for (int j = 0; j < 100; j++) acc += l1s[j] * w[j];
            l2s[tid] = fmaxf(acc, 0.f);
        }
        __syncthreads();
        if (tid == 0) {
            float y = b3[0];
            for (int j = 0; j < 50; j++) y += l2s[j] * W3[j];
            out[b * 5 + st] = y;
            xs = y;
        }
        __syncthreads();
        xv = xs;
    }
}

extern "C" void kernel_launch(void* const* d_in, const int* in_sizes, int n_in,
                              void* d_out, int out_size) {
    const float* x   = (const float*)d_in[0];
    const float* h0  = (const float*)d_in[1];
    const float* c0  = (const float*)d_in[2];
    const float* enc = (const float*)d_in[3];
    const float* Wa  = (const float*)d_in[4];
    const float* ba  = (const float*)d_in[5];
    const float* Ua  = (const float*)d_in[6];
    const float* bua = (const float*)d_in[7];
    const float* Va  = (const float*)d_in[8];
    const float* bva = (const float*)d_in[9];
    const float* Wih = (const float*)d_in[10];
    const float* Whh = (const float*)d_in[11];
    const float* bih = (const float*)d_in[12];
    const float* bhh = (const float*)d_in[13];
    const float* W1  = (const float*)d_in[14];
    const float* b1  = (const float*)d_in[15];
    const float* W2  = (const float*)d_in[16];
    const float* b2  = (const float*)d_in[17];
    const float* W3  = (const float*)d_in[18];
    const float* b3  = (const float*)d_in[19];
    float* out = (float*)d_out;

    prep_ua<<<HP, 256>>>(Ua);
    prep_qh<<<B_, 256>>>(h0, Wa, ba, bua, Whh, bhh);

    int smem = 128 * LD * 2 + HP * LD * 2 + (8 * 320 + HP + HP) * 4;  // 157056 B
    cudaFuncSetAttribute(scores_k, cudaFuncAttributeMaxDynamicSharedMemorySize, smem);
    scores_k<<<B_ * 16, 256, smem>>>(enc, Va, bva);

    softmax_k<<<B_, 256>>>();
    context_k<<<dim3(B_, 16), 256>>>(enc);
    decoder_k<<<B_, 256>>>(x, c0, Wih, bih, W1, b1, W2, b2, W3, b3, out);
}

// round 3
// speedup vs baseline: 1.3278x; 1.3278x over previous
#include <cuda_runtime.h>
#include <cuda_fp16.h>
#include <cstdint>

#define B_  128
#define T_  2048
#define H_  200
#define HP  208          // N padded to 16
#define LD  216          // smem leading dim in halves (432B rows: 27x16B, odd -> LDSM conflict-free)
#define G4  800

// ---------------- device scratch ----------------
__device__ __align__(16) half g_Ua[HP * LD];   // Ua fp16, [n][k] row-major, zero-padded
__device__ float g_qadd[B_ * HP];
__device__ float g_hpre[B_ * G4];
__device__ float g_sc[B_ * T_];
__device__ float g_ctxp[16 * B_ * H_];

// ---------------- helpers ----------------
__device__ __forceinline__ uint32_t smem_u32(const void* p) {
    uint32_t a;
    asm("{ .reg .u64 t; cvta.to.shared.u64 t, %1; cvt.u32.u64 %0, t; }" : "=r"(a) : "l"(p));
    return a;
}
__device__ __forceinline__ void ldsm4(uint32_t* r, uint32_t addr) {
    asm volatile("ldmatrix.sync.aligned.m8n8.x4.shared.b16 {%0,%1,%2,%3}, [%4];"
                 : "=r"(r[0]), "=r"(r[1]), "=r"(r[2]), "=r"(r[3]) : "r"(addr));
}
__device__ __forceinline__ void mma16816(float* d, const uint32_t* a, uint32_t b0, uint32_t b1) {
    asm volatile("mma.sync.aligned.m16n8k16.row.col.f32.f16.f16.f32 "
                 "{%0,%1,%2,%3}, {%4,%5,%6,%7}, {%8,%9}, {%0,%1,%2,%3};"
                 : "+f"(d[0]), "+f"(d[1]), "+f"(d[2]), "+f"(d[3])
                 : "r"(a[0]), "r"(a[1]), "r"(a[2]), "r"(a[3]), "r"(b0), "r"(b1));
}
__device__ __forceinline__ float tanh_fast(float x) {
    float y;
    asm("tanh.approx.f32 %0, %1;" : "=f"(y) : "f"(x));
    return y;
}
__device__ __forceinline__ float fast_sig(float x) {
    return __fdividef(1.f, 1.f + __expf(-x));
}
__device__ __forceinline__ float ref_tanh(float x) {       // higher-accuracy tanh for LSTM cell
    float e = __expf(2.f * x);
    return 1.f - __fdividef(2.f, e + 1.f);
}
__device__ __forceinline__ float wred(float v) {
    v += __shfl_xor_sync(~0u, v, 16); v += __shfl_xor_sync(~0u, v, 8);
    v += __shfl_xor_sync(~0u, v, 4);  v += __shfl_xor_sync(~0u, v, 2);
    v += __shfl_xor_sync(~0u, v, 1);  return v;
}

// -------- prep: Ua -> fp16 [n][LD] row-major, zero-padded --------
__global__ void prep_ua(const float* __restrict__ Ua) {
    int n = blockIdx.x, k = threadIdx.x;
    if (k < LD) {
        float v = (n < H_ && k < H_) ? Ua[n * H_ + k] : 0.f;
        g_Ua[n * LD + k] = __float2half(v);
    }
}

// -------- prep: qadd + h_pre, warp-cooperative coalesced dots --------
__global__ void prep_qh(const float* __restrict__ h0, const float* __restrict__ Wa,
                        const float* __restrict__ ba, const float* __restrict__ bua,
                        const float* __restrict__ Whh, const float* __restrict__ bhh) {
    int b = blockIdx.x, tid = threadIdx.x, wid = tid >> 5, lid = tid & 31;
    __shared__ float hs[H_];
    if (tid < H_) hs[tid] = h0[b * H_ + tid];
    __syncthreads();
    for (int r = wid; r < HP; r += 8) {
        float acc = 0.f;
        if (r < H_) {
            const float* w = Wa + r * H_;
            for (int k = lid; k < H_; k += 32) acc += hs[k] * w[k];
        }
        acc = wred(acc);
        if (lid == 0) g_qadd[b * HP + r] = (r < H_) ? acc + ba[r] + bua[r] : 0.f;
    }
    for (int r = wid; r < G4; r += 8) {
        const float* w = Whh + r * H_;
        float acc = 0.f;
        for (int k = lid; k < H_; k += 32) acc += hs[k] * w[k];
        acc = wred(acc);
        if (lid == 0) g_hpre[b * G4 + r] = acc + bhh[r];
    }
}

// -------- fused scores via raw mma.sync (HMMA): tanh(qadd + enc@Ua.T) . Va + bva --------
// grid 2048 (16 tiles/batch, 128 rows each), 256 threads = 8 warps x 16 rows
#define SM_AS   0
#define SM_BS   (128 * LD * 2)                 // 55296
#define SM_QV   (SM_BS + HP * LD * 2)          // 55296 + 89856 = 145152
#define SM_TOT  (SM_QV + HP * 8 + 16)          // ~146832

__global__ void __launch_bounds__(256) scores_k(const float* __restrict__ enc,
                                                const float* __restrict__ Va,
                                                const float* __restrict__ bva) {
    extern __shared__ char sm[];
    half*   As = (half*)(sm + SM_AS);
    half*   Bs = (half*)(sm + SM_BS);
    float2* qv = (float2*)(sm + SM_QV);

    int tid = threadIdx.x, wid = tid >> 5, lid = tid & 31;
    int b  = blockIdx.x >> 4;
    int t0 = (blockIdx.x & 15) << 7;

    // stage Ua (already fp16 [n][LD]) via 16B copies
    {
        const uint4* s4 = (const uint4*)g_Ua;
        uint4* d4 = (uint4*)Bs;
        for (int i = tid; i < (HP * LD * 2) / 16; i += 256) d4[i] = s4[i];
    }
    if (tid < HP) qv[tid] = make_float2(g_qadd[b * HP + tid], (tid < H_) ? Va[tid] : 0.f);

    // stage 128 encoder rows fp32 -> fp16 (LD/8 = 27 octs per row; octs 25,26 zero pad)
    const float* encb = enc + (size_t)(b * T_ + t0) * H_;
    for (int u = tid; u < 128 * 27; u += 256) {
        int row = u / 27, oc = u % 27, k = oc * 8;
        uint4 v;
        half2* hp = (half2*)&v;
        if (k < H_) {
            const float4 f0 = *(const float4*)(encb + row * H_ + k);
            const float4 f1 = *(const float4*)(encb + row * H_ + k + 4);
            hp[0] = __floats2half2_rn(f0.x, f0.y);
            hp[1] = __floats2half2_rn(f0.z, f0.w);
            hp[2] = __floats2half2_rn(f1.x, f1.y);
            hp[3] = __floats2half2_rn(f1.z, f1.w);
        } else {
            v = make_uint4(0, 0, 0, 0);
        }
        *(uint4*)(As + row * LD + k) = v;
    }
    __syncthreads();

    // per-lane ldmatrix addressing
    int lr = lid & 7, quad = lid >> 3;           // quad selects which 8x8 matrix this lane addresses
    // A matrices order: {r0-7,k0},{r8-15,k0},{r0-7,k8},{r8-15,k8}
    uint32_t a_base = smem_u32(As) + (uint32_t)(((wid * 16) + (quad & 1) * 8 + lr) * LD + (quad >> 1) * 8) * 2u;
    // B matrices order: {n0-7,k0},{n0-7,k8},{n8-15,k0},{n8-15,k8}  -> regs {b00,b01,b10,b11}
    uint32_t b_base = smem_u32(Bs) + (uint32_t)((((quad >> 1) * 8) + lr) * LD + (quad & 1) * 8) * 2u;

    // A fragments cached once: 13 k-steps
    uint32_t afr[13][4];
    #pragma unroll
    for (int s = 0; s < 13; s++) ldsm4(afr[s], a_base + (uint32_t)(s * 32));

    float pA = 0.f, pB = 0.f;                    // rows r and r+8 partial score dots
    int cq = (lid & 3) * 2;                      // col base within 8-wide n-tile

    for (int p = 0; p < 13; p++) {               // n-pairs: n0 = 32*quadrant... n0 = p*16
        float c0[4] = {0.f, 0.f, 0.f, 0.f};
        float c1[4] = {0.f, 0.f, 0.f, 0.f};
        uint32_t bp = b_base + (uint32_t)(p * 16 * LD * 2);
        #pragma unroll
        for (int s = 0; s < 13; s++) {
            uint32_t bb[4];
            ldsm4(bb, bp + (uint32_t)(s * 32));
            mma16816(c0, afr[s], bb[0], bb[1]);
            mma16816(c1, afr[s], bb[2], bb[3]);
        }
        int n0 = p * 16 + cq;
        float2 q0 = qv[n0],      q1 = qv[n0 + 1];
        float2 q2 = qv[n0 + 8],  q3 = qv[n0 + 9];
        pA += q0.y * tanh_fast(q0.x + c0[0]);
        pA += q1.y * tanh_fast(q1.x + c0[1]);
        pB += q0.y * tanh_fast(q0.x + c0[2]);
        pB += q1.y * tanh_fast(q1.x + c0[3]);
        pA += q2.y * tanh_fast(q2.x + c1[0]);
        pA += q3.y * tanh_fast(q3.x + c1[1]);
        pB += q2.y * tanh_fast(q2.x + c1[2]);
        pB += q3.y * tanh_fast(q3.x + c1[3]);
    }
    // reduce across the 4 lanes sharing a row-group
    pA += __shfl_xor_sync(~0u, pA, 1); pA += __shfl_xor_sync(~0u, pA, 2);
    pB += __shfl_xor_sync(~0u, pB, 1); pB += __shfl_xor_sync(~0u, pB, 2);
    if ((lid & 3) == 0) {
        float bv = bva[0];
        int r = lid >> 2;
        g_sc[b * T_ + t0 + wid * 16 + r]     = pA + bv;
        g_sc[b * T_ + t0 + wid * 16 + r + 8] = pB + bv;
    }
}

// -------- softmax over T per batch, in place --------
__global__ void softmax_k() {
    int b = blockIdx.x, tid = threadIdx.x;
    __shared__ float red[256];
    float* s = g_sc + b * T_;
    float m = -1e30f;
    for (int i = tid; i < T_; i += 256) m = fmaxf(m, s[i]);
    red[tid] = m; __syncthreads();
    for (int st = 128; st > 0; st >>= 1) { if (tid < st) red[tid] = fmaxf(red[tid], red[tid + st]); __syncthreads(); }
    m = red[0]; __syncthreads();
    float sum = 0.f;
    for (int i = tid; i < T_; i += 256) { float e = __expf(s[i] - m); s[i] = e; sum += e; }
    red[tid] = sum; __syncthreads();
    for (int st = 128; st > 0; st >>= 1) { if (tid < st) red[tid] += red[tid + st]; __syncthreads(); }
    float inv = 1.f / red[0];
    for (int i = tid; i < T_; i += 256) s[i] *= inv;
}

// -------- context partials (deterministic 16-way split) --------
__global__ void context_k(const float* __restrict__ enc) {
    int b = blockIdx.x, s = blockIdx.y, tid = threadIdx.x;
    __shared__ float w[128];
    if (tid < 128) w[tid] = g_sc[b * T_ + s * 128 + tid];
    __syncthreads();
    if (tid < H_) {
        const float* p = enc + (size_t)(b * T_ + s * 128) * H_ + tid;
        float acc = 0.f;
        #pragma unroll 8
        for (int t = 0; t < 128; t++) acc += w[t] * p[(size_t)t * H_];
        g_ctxp[(s * B_ + b) * H_ + tid] = acc;
    }
}

// -------- decoder: warp-cooperative coalesced GEMVs + 5 tiny steps --------
__global__ void decoder_k(const float* __restrict__ x,  const float* __restrict__ c0,
                          const float* __restrict__ Wih, const float* __restrict__ bih,
                          const float* __restrict__ W1, const float* __restrict__ b1,
                          const float* __restrict__ W2, const float* __restrict__ b2,
                          const float* __restrict__ W3, const float* __restrict__ b3,
                          float* __restrict__ out) {
    int b = blockIdx.x, tid = threadIdx.x, wid = tid >> 5, lid = tid & 31;
    __shared__ float ctx[H_], gb[G4], wcol[G4], c0s[H_], r0s[H_], l1s[100], l2s[50];
    __shared__ float xs;
    if (tid < H_) {
        float a = 0.f;
        #pragma unroll
        for (int j = 0; j < 16; j++) a += g_ctxp[(j * B_ + b) * H_ + tid];
        ctx[tid] = a;
        c0s[tid] = c0[b * H_ + tid];
    }
    if (tid == 0) xs = x[b];
    for (int g = tid; g < G4; g += 256) wcol[g] = Wih[g * 201];
    __syncthreads();
    for (int g = wid; g < G4; g += 8) {
        const float* w = Wih + g * 201 + 1;
        float acc = 0.f;
        for (int k = lid; k < H_; k += 32) acc += ctx[k] * w[k];
        acc = wred(acc);
        if (lid == 0) gb[g] = acc + bih[g] + g_hpre[b * G4 + g];
    }
    __syncthreads();
    float xv = xs;
    for (int st = 0; st < 5; st++) {
        if (tid < H_) {
            float gi = gb[tid]          + xv * wcol[tid];
            float gf = gb[H_ + tid]     + xv * wcol[H_ + tid];
            float gg = gb[2 * H_ + tid] + xv * wcol[2 * H_ + tid];
            float go = gb[3 * H_ + tid] + xv * wcol[3 * H_ + tid];
            float c  = fast_sig(gf) * c0s[tid] + fast_sig(gi) * ref_tanh(gg);
            float h  = fast_sig(go) * ref_tanh(c);
            r0s[tid] = fmaxf(h, 0.f);
        }
        __syncthreads();
        for (int r = wid; r < 100; r += 8) {
            const float* w = W1 + r * H_;
            float acc = 0.f;
            for (int k = lid; k < H_; k += 32) acc += r0s[k] * w[k];
            acc = wred(acc);
            if (lid == 0) l1s[r] = fmaxf(acc + b1[r], 0.f);
        }
        __syncthreads();
        for (int r = wid; r < 50; r += 8) {
            const float* w = W2 + r * 100;
            float acc = 0.f;
            for (int k = lid; k < 100; k += 32) acc += l1s[k] * w[k];
            acc = wred(acc);
            if (lid == 0) l2s[r] = fmaxf(acc + b2[r], 0.f);
        }
        __syncthreads();
        if (wid == 0) {
            float acc = 0.f;
            for (int k = lid; k < 50; k += 32) acc += l2s[k] * W3[k];
            acc = wred(acc);
            if (lid == 0) { float y = acc + b3[0]; out[b * 5 + st] = y; xs = y; }
        }
        __syncthreads();
        xv = xs;
    }
}

extern "C" void kernel_launch(void* const* d_in, const int* in_sizes, int n_in,
                              void* d_out, int out_size) {
    const float* x   = (const float*)d_in[0];
    const float* h0  = (const float*)d_in[1];
    const float* c0  = (const float*)d_in[2];
    const float* enc = (const float*)d_in[3];
    const float* Wa  = (const float*)d_in[4];
    const float* ba  = (const float*)d_in[5];
    const float* Ua  = (const float*)d_in[6];
    const float* bua = (const float*)d_in[7];
    const float* Va  = (const float*)d_in[8];
    const float* bva = (const float*)d_in[9];
    const float* Wih = (const float*)d_in[10];
    const float* Whh = (const float*)d_in[11];
    const float* bih = (const float*)d_in[12];
    const float* bhh = (const float*)d_in[13];
    const float* W1  = (const float*)d_in[14];
    const float* b1  = (const float*)d_in[15];
    const float* W2  = (const float*)d_in[16];
    const float* b2  = (const float*)d_in[17];
    const float* W3  = (const float*)d_in[18];
    const float* b3  = (const float*)d_in[19];
    float* out = (float*)d_out;

    prep_ua<<<HP, 256>>>(Ua);
    prep_qh<<<B_, 256>>>(h0, Wa, ba, bua, Whh, bhh);

    cudaFuncSetAttribute(scores_k, cudaFuncAttributeMaxDynamicSharedMemorySize, SM_TOT);
    scores_k<<<B_ * 16, 256, SM_TOT>>>(enc, Va, bva);

    softmax_k<<<B_, 256>>>();
    context_k<<<dim3(B_, 16), 256>>>(enc);
    decoder_k<<<B_, 256>>>(x, c0, Wih, bih, W1, b1, W2, b2, W3, b3, out);
}

// round 4
// speedup vs baseline: 1.3998x; 1.0542x over previous
#include <cuda_runtime.h>
#include <cuda_fp16.h>
#include <cstdint>

#define B_  128
#define T_  2048
#define H_  200
#define HP  208          // N padded to 16
#define LD  216          // smem leading dim in halves (432B rows, conflict-free for ldmatrix)
#define G4  800

// ---------------- device scratch ----------------
__device__ __align__(16) half g_Ua[HP * LD];   // Ua fp16, [n][k] row-major, zero-padded
__device__ float g_qadd[B_ * HP];
__device__ float g_hpre[B_ * G4];
__device__ float g_sc[B_ * T_];
__device__ float g_ctxp[16 * B_ * H_];

// ---------------- helpers ----------------
__device__ __forceinline__ uint32_t smem_u32(const void* p) {
    uint32_t a;
    asm("{ .reg .u64 t; cvta.to.shared.u64 t, %1; cvt.u32.u64 %0, t; }" : "=r"(a) : "l"(p));
    return a;
}
__device__ __forceinline__ void ldsm4(uint32_t* r, uint32_t addr) {
    asm volatile("ldmatrix.sync.aligned.m8n8.x4.shared.b16 {%0,%1,%2,%3}, [%4];"
                 : "=r"(r[0]), "=r"(r[1]), "=r"(r[2]), "=r"(r[3]) : "r"(addr));
}
__device__ __forceinline__ void mma16816(float* d, const uint32_t* a, uint32_t b0, uint32_t b1) {
    asm volatile("mma.sync.aligned.m16n8k16.row.col.f32.f16.f16.f32 "
                 "{%0,%1,%2,%3}, {%4,%5,%6,%7}, {%8,%9}, {%0,%1,%2,%3};"
                 : "+f"(d[0]), "+f"(d[1]), "+f"(d[2]), "+f"(d[3])
                 : "r"(a[0]), "r"(a[1]), "r"(a[2]), "r"(a[3]), "r"(b0), "r"(b1));
}
__device__ __forceinline__ float tanh_fast(float x) {
    float y;
    asm("tanh.approx.f32 %0, %1;" : "=f"(y) : "f"(x));
    return y;
}
__device__ __forceinline__ float fast_sig(float x) {
    return __fdividef(1.f, 1.f + __expf(-x));
}
__device__ __forceinline__ float ref_tanh(float x) {
    float e = __expf(2.f * x);
    return 1.f - __fdividef(2.f, e + 1.f);
}
__device__ __forceinline__ float wred(float v) {
    v += __shfl_xor_sync(~0u, v, 16); v += __shfl_xor_sync(~0u, v, 8);
    v += __shfl_xor_sync(~0u, v, 4);  v += __shfl_xor_sync(~0u, v, 2);
    v += __shfl_xor_sync(~0u, v, 1);  return v;
}

// -------- prep: Ua -> fp16 [n][LD] row-major, zero-padded --------
__global__ void prep_ua(const float* __restrict__ Ua) {
    int n = blockIdx.x, k = threadIdx.x;
    if (k < LD) {
        float v = (n < H_ && k < H_) ? Ua[n * H_ + k] : 0.f;
        g_Ua[n * LD + k] = __float2half(v);
    }
}

// -------- prep: qadd (warp-cooperative coalesced) --------
__global__ void prep_q(const float* __restrict__ h0, const float* __restrict__ Wa,
                       const float* __restrict__ ba, const float* __restrict__ bua) {
    int b = blockIdx.x, tid = threadIdx.x, wid = tid >> 5, lid = tid & 31;
    __shared__ float hs[H_];
    if (tid < H_) hs[tid] = h0[b * H_ + tid];
    __syncthreads();
    for (int r = wid; r < HP; r += 8) {
        float acc = 0.f;
        if (r < H_) {
            const float* w = Wa + r * H_;
            for (int k = lid; k < H_; k += 32) acc += hs[k] * w[k];
        }
        acc = wred(acc);
        if (lid == 0) g_qadd[b * HP + r] = (r < H_) ? acc + ba[r] + bua[r] : 0.f;
    }
}

// -------- prep: h_pre (warp-cooperative coalesced) --------
__global__ void prep_h(const float* __restrict__ h0, const float* __restrict__ Whh,
                       const float* __restrict__ bhh) {
    int b = blockIdx.x, tid = threadIdx.x, wid = tid >> 5, lid = tid & 31;
    __shared__ float hs[H_];
    if (tid < H_) hs[tid] = h0[b * H_ + tid];
    __syncthreads();
    for (int r = wid; r < G4; r += 8) {
        const float* w = Whh + r * H_;
        float acc = 0.f;
        for (int k = lid; k < H_; k += 32) acc += hs[k] * w[k];
        acc = wred(acc);
        if (lid == 0) g_hpre[b * G4 + r] = acc + bhh[r];
    }
}

// -------- fused scores via raw mma.sync, max chain parallelism --------
// 512 threads = 16 warps: warp w -> row group (w&7)*16, n-half (w>>3)
// n-half 0: n-pairs p in [0,7); n-half 1: p in [7,13)
#define SM_AS   0
#define SM_BS   (128 * LD * 2)                   // 55296
#define SM_QV   (SM_BS + HP * LD * 2)            // 145152
#define SM_SP   (SM_QV + HP * 8)                 // 146816  partial scores [2][128]
#define SM_TOT  (SM_SP + 256 * 4)                // 147840

__global__ void __launch_bounds__(512) scores_k(const float* __restrict__ enc,
                                                const float* __restrict__ Va,
                                                const float* __restrict__ bva) {
    extern __shared__ char sm[];
    half*   As = (half*)(sm + SM_AS);
    half*   Bs = (half*)(sm + SM_BS);
    float2* qv = (float2*)(sm + SM_QV);
    float*  sp = (float*)(sm + SM_SP);

    int tid = threadIdx.x, wid = tid >> 5, lid = tid & 31;
    int b  = blockIdx.x >> 4;
    int t0 = (blockIdx.x & 15) << 7;

    // stage Ua (already fp16 [n][LD]) via 16B copies
    {
        const uint4* s4 = (const uint4*)g_Ua;
        uint4* d4 = (uint4*)Bs;
        for (int i = tid; i < (HP * LD * 2) / 16; i += 512) d4[i] = s4[i];
    }
    if (tid < HP) qv[tid] = make_float2(g_qadd[b * HP + tid], (tid < H_) ? Va[tid] : 0.f);

    // stage 128 encoder rows fp32 -> fp16 (27 octs per row; octs 25,26 zero pad)
    const float* encb = enc + (size_t)(b * T_ + t0) * H_;
    for (int u = tid; u < 128 * 27; u += 512) {
        int row = u / 27, oc = u % 27, k = oc * 8;
        uint4 v;
        half2* hp = (half2*)&v;
        if (k < H_) {
            const float4 f0 = *(const float4*)(encb + row * H_ + k);
            const float4 f1 = *(const float4*)(encb + row * H_ + k + 4);
            hp[0] = __floats2half2_rn(f0.x, f0.y);
            hp[1] = __floats2half2_rn(f0.z, f0.w);
            hp[2] = __floats2half2_rn(f1.x, f1.y);
            hp[3] = __floats2half2_rn(f1.z, f1.w);
        } else {
            v = make_uint4(0, 0, 0, 0);
        }
        *(uint4*)(As + row * LD + k) = v;
    }
    __syncthreads();

    int rg = wid & 7, nh = wid >> 3;
    int lr = lid & 7, quad = lid >> 3;
    // A matrices: {r0-7,k0},{r8-15,k0},{r0-7,k8},{r8-15,k8}
    uint32_t a_base = smem_u32(As) + (uint32_t)(((rg * 16) + (quad & 1) * 8 + lr) * LD + (quad >> 1) * 8) * 2u;
    // B matrices: {n0-7,k0},{n0-7,k8},{n8-15,k0},{n8-15,k8}
    uint32_t b_base = smem_u32(Bs) + (uint32_t)((((quad >> 1) * 8) + lr) * LD + (quad & 1) * 8) * 2u;

    // A fragments cached once: 13 k-steps
    uint32_t afr[13][4];
    #pragma unroll
    for (int s = 0; s < 13; s++) ldsm4(afr[s], a_base + (uint32_t)(s * 32));

    float pA = 0.f, pB = 0.f;
    int cq = (lid & 3) * 2;
    int p0 = nh ? 7 : 0, p1 = nh ? 13 : 7;

    int p = p0;
    // paired n-tiles: 8 independent accumulator chains (2 p x 2 n-sub x 2 k-halves)
    for (; p + 1 < p1; p += 2) {
        float acc[8][4];
        #pragma unroll
        for (int i = 0; i < 8; i++)
            #pragma unroll
            for (int j = 0; j < 4; j++) acc[i][j] = 0.f;
        uint32_t bpA = b_base + (uint32_t)(p * 16 * LD * 2);
        uint32_t bpB = bpA + (uint32_t)(16 * LD * 2);
        #pragma unroll
        for (int s = 0; s < 13; s++) {
            int o = (s < 6) ? 0 : 4;
            uint32_t ba_[4], bb_[4];
            ldsm4(ba_, bpA + (uint32_t)(s * 32));
            ldsm4(bb_, bpB + (uint32_t)(s * 32));
            mma16816(acc[o + 0], afr[s], ba_[0], ba_[1]);
            mma16816(acc[o + 1], afr[s], ba_[2], ba_[3]);
            mma16816(acc[o + 2], afr[s], bb_[0], bb_[1]);
            mma16816(acc[o + 3], afr[s], bb_[2], bb_[3]);
        }
        #pragma unroll
        for (int t = 0; t < 2; t++) {            // t=0 -> p, t=1 -> p+1
            int n0 = (p + t) * 16 + cq;
            float2 q0 = qv[n0],     q1 = qv[n0 + 1];
            float2 q2 = qv[n0 + 8], q3 = qv[n0 + 9];
            float* cL = acc[t * 2];              // acc[0]/acc[2]
            float* cLk = acc[t * 2 + 4];
            float* cH = acc[t * 2 + 1];          // acc[1]/acc[3]
            float* cHk = acc[t * 2 + 5];
            pA += q0.y * tanh_fast(q0.x + cL[0] + cLk[0]);
            pA += q1.y * tanh_fast(q1.x + cL[1] + cLk[1]);
            pB += q0.y * tanh_fast(q0.x + cL[2] + cLk[2]);
            pB += q1.y * tanh_fast(q1.x + cL[3] + cLk[3]);
            pA += q2.y * tanh_fast(q2.x + cH[0] + cHk[0]);
            pA += q3.y * tanh_fast(q3.x + cH[1] + cHk[1]);
            pB += q2.y * tanh_fast(q2.x + cH[2] + cHk[2]);
            pB += q3.y * tanh_fast(q3.x + cH[3] + cHk[3]);
        }
    }
    if (p < p1) {                                // odd remainder: 4 chains
        float acc[4][4];
        #pragma unroll
        for (int i = 0; i < 4; i++)
            #pragma unroll
            for (int j = 0; j < 4; j++) acc[i][j] = 0.f;
        uint32_t bpA = b_base + (uint32_t)(p * 16 * LD * 2);
        #pragma unroll
        for (int s = 0; s < 13; s++) {
            int o = (s < 6) ? 0 : 2;
            uint32_t ba_[4];
            ldsm4(ba_, bpA + (uint32_t)(s * 32));
            mma16816(acc[o + 0], afr[s], ba_[0], ba_[1]);
            mma16816(acc[o + 1], afr[s], ba_[2], ba_[3]);
        }
        int n0 = p * 16 + cq;
        float2 q0 = qv[n0],     q1 = qv[n0 + 1];
        float2 q2 = qv[n0 + 8], q3 = qv[n0 + 9];
        pA += q0.y * tanh_fast(q0.x + acc[0][0] + acc[2][0]);
        pA += q1.y * tanh_fast(q1.x + acc[0][1] + acc[2][1]);
        pB += q0.y * tanh_fast(q0.x + acc[0][2] + acc[2][2]);
        pB += q1.y * tanh_fast(q1.x + acc[0][3] + acc[2][3]);
        pA += q2.y * tanh_fast(q2.x + acc[1][0] + acc[3][0]);
        pA += q3.y * tanh_fast(q3.x + acc[1][1] + acc[3][1]);
        pB += q2.y * tanh_fast(q2.x + acc[1][2] + acc[3][2]);
        pB += q3.y * tanh_fast(q3.x + acc[1][3] + acc[3][3]);
    }

    // intra-warp reduce over the 4 lanes sharing each row
    pA += __shfl_xor_sync(~0u, pA, 1); pA += __shfl_xor_sync(~0u, pA, 2);
    pB += __shfl_xor_sync(~0u, pB, 1); pB += __shfl_xor_sync(~0u, pB, 2);
    if ((lid & 3) == 0) {
        int r = lid >> 2;
        sp[nh * 128 + rg * 16 + r]     = pA;
        sp[nh * 128 + rg * 16 + r + 8] = pB;
    }
    __syncthreads();
    // cross-n-half reduce + bias
    if (tid < 128)
        g_sc[b * T_ + t0 + tid] = sp[tid] + sp[128 + tid] + bva[0];
}

// -------- softmax over T per batch, in place --------
__global__ void softmax_k() {
    int b = blockIdx.x, tid = threadIdx.x;
    __shared__ float red[256];
    float* s = g_sc + b * T_;
    float m = -1e30f;
    for (int i = tid; i < T_; i += 256) m = fmaxf(m, s[i]);
    red[tid] = m; __syncthreads();
    for (int st = 128; st > 0; st >>= 1) { if (tid < st) red[tid] = fmaxf(red[tid], red[tid + st]); __syncthreads(); }
    m = red[0]; __syncthreads();
    float sum = 0.f;
    for (int i = tid; i < T_; i += 256) { float e = __expf(s[i] - m); s[i] = e; sum += e; }
    red[tid] = sum; __syncthreads();
    for (int st = 128; st > 0; st >>= 1) { if (tid < st) red[tid] += red[tid + st]; __syncthreads(); }
    float inv = 1.f / red[0];
    for (int i = tid; i < T_; i += 256) s[i] *= inv;
}

// -------- context partials (deterministic 16-way split) --------
__global__ void context_k(const float* __restrict__ enc) {
    int b = blockIdx.x, s = blockIdx.y, tid = threadIdx.x;
    __shared__ float w[128];
    if (tid < 128) w[tid] = g_sc[b * T_ + s * 128 + tid];
    __syncthreads();
    if (tid < H_) {
        const float* p = enc + (size_t)(b * T_ + s * 128) * H_ + tid;
        float acc = 0.f;
        #pragma unroll 8
        for (int t = 0; t < 128; t++) acc += w[t] * p[(size_t)t * H_];
        g_ctxp[(s * B_ + b) * H_ + tid] = acc;
    }
}

// -------- decoder: warp-cooperative coalesced GEMVs + 5 tiny steps --------
__global__ void decoder_k(const float* __restrict__ x,  const float* __restrict__ c0,
                          const float* __restrict__ Wih, const float* __restrict__ bih,
                          const float* __restrict__ W1, const float* __restrict__ b1,
                          const float* __restrict__ W2, const float* __restrict__ b2,
                          const float* __restrict__ W3, const float* __restrict__ b3,
                          float* __restrict__ out) {
    int b = blockIdx.x, tid = threadIdx.x, wid = tid >> 5, lid = tid & 31;
    __shared__ float ctx[H_], gb[G4], wcol[G4], c0s[H_], r0s[H_], l1s[100], l2s[50];
    __shared__ float xs;
    if (tid < H_) {
        float a = 0.f;
        #pragma unroll
        for (int j = 0; j < 16; j++) a += g_ctxp[(j * B_ + b) * H_ + tid];
        ctx[tid] = a;
        c0s[tid] = c0[b * H_ + tid];
    }
    if (tid == 0) xs = x[b];
    for (int g = tid; g < G4; g += 256) wcol[g] = Wih[g * 201];
    __syncthreads();
    for (int g = wid; g < G4; g += 8) {
        const float* w = Wih + g * 201 + 1;
        float acc = 0.f;
        for (int k = lid; k < H_; k += 32) acc += ctx[k] * w[k];
        acc = wred(acc);
        if (lid == 0) gb[g] = acc + bih[g] + g_hpre[b * G4 + g];
    }
    __syncthreads();
    float xv = xs;
    for (int st = 0; st < 5; st++) {
        if (tid < H_) {
            float gi = gb[tid]          + xv * wcol[tid];
            float gf = gb[H_ + tid]     + xv * wcol[H_ + tid];
            float gg = gb[2 * H_ + tid] + xv * wcol[2 * H_ + tid];
            float go = gb[3 * H_ + tid] + xv * wcol[3 * H_ + tid];
            float c  = fast_sig(gf) * c0s[tid] + fast_sig(gi) * ref_tanh(gg);
            float h  = fast_sig(go) * ref_tanh(c);
            r0s[tid] = fmaxf(h, 0.f);
        }
        __syncthreads();
        for (int r = wid; r < 100; r += 8) {
            const float* w = W1 + r * H_;
            float acc = 0.f;
            for (int k = lid; k < H_; k += 32) acc += r0s[k] * w[k];
            acc = wred(acc);
            if (lid == 0) l1s[r] = fmaxf(acc + b1[r], 0.f);
        }
        __syncthreads();
        for (int r = wid; r < 50; r += 8) {
            const float* w = W2 + r * 100;
            float acc = 0.f;
            for (int k = lid; k < 100; k += 32) acc += l1s[k] * w[k];
            acc = wred(acc);
            if (lid == 0) l2s[r] = fmaxf(acc + b2[r], 0.f);
        }
        __syncthreads();
        if (wid == 0) {
            float acc = 0.f;
            for (int k = lid; k < 50; k += 32) acc += l2s[k] * W3[k];
            acc = wred(acc);
            if (lid == 0) { float y = acc + b3[0]; out[b * 5 + st] = y; xs = y; }
        }
        __syncthreads();
        xv = xs;
    }
}

extern "C" void kernel_launch(void* const* d_in, const int* in_sizes, int n_in,
                              void* d_out, int out_size) {
    const float* x   = (const float*)d_in[0];
    const float* h0  = (const float*)d_in[1];
    const float* c0  = (const float*)d_in[2];
    const float* enc = (const float*)d_in[3];
    const float* Wa  = (const float*)d_in[4];
    const float* ba  = (const float*)d_in[5];
    const float* Ua  = (const float*)d_in[6];
    const float* bua = (const float*)d_in[7];
    const float* Va  = (const float*)d_in[8];
    const float* bva = (const float*)d_in[9];
    const float* Wih = (const float*)d_in[10];
    const float* Whh = (const float*)d_in[11];
    const float* bih = (const float*)d_in[12];
    const float* bhh = (const float*)d_in[13];
    const float* W1  = (const float*)d_in[14];
    const float* b1  = (const float*)d_in[15];
    const float* W2  = (const float*)d_in[16];
    const float* b2  = (const float*)d_in[17];
    const float* W3  = (const float*)d_in[18];
    const float* b3  = (const float*)d_in[19];
    float* out = (float*)d_out;

    prep_ua<<<HP, 256>>>(Ua);                       // launch 1
    prep_q<<<B_, 256>>>(h0, Wa, ba, bua);           // launch 2
    prep_h<<<B_, 256>>>(h0, Whh, bhh);              // launch 3

    cudaFuncSetAttribute(scores_k, cudaFuncAttributeMaxDynamicSharedMemorySize, SM_TOT);
    scores_k<<<B_ * 16, 512, SM_TOT>>>(enc, Va, bva);  // launch 4 <- ncu capture slot

    softmax_k<<<B_, 256>>>();
    context_k<<<dim3(B_, 16), 256>>>(enc);
    decoder_k<<<B_, 256>>>(x, c0, Wih, bih, W1, b1, W2, b2, W3, b3, out);
}